// round 11
// baseline (speedup 1.0000x reference)
#include <cuda_runtime.h>
#include <cuda_bf16.h>
#include <cuda_fp16.h>
#include <cstdint>

#define NB 16
#define NQT 2048
#define NKT 2048
#define ND 1024
#define NTHREADS 256

#define NEG_INF __int_as_float(0xff800000)

// ---- device-global scratch (no cudaMalloc allowed) ----
// Q A-fragments (bf16 hi/lo): [b][qtile16(128)][chunk16(64)][hi/lo(2)][lane(32)] uint4
__device__ uint4 g_QA[16 * 128 * 64 * 2 * 32];
// K B-fragments (bf16 hi/lo): [b][ntile8(256)][chunk16(64)][hi/lo(2)][lane(32)] uint2
__device__ uint2 g_KB[16 * 256 * 64 * 2 * 32];
// V B-fragments (fp16): [b][kchunk16(128)][ntile8(128)][lane(32)] uint2
__device__ uint2 g_VH[16 * 128 * 128 * 32];
__device__ float g_meanV[NB * ND];

__device__ __forceinline__ void mma_bf16(float& c0, float& c1, float& c2, float& c3,
                                         const uint4& a, unsigned b0, unsigned b1) {
    asm volatile("mma.sync.aligned.m16n8k16.row.col.f32.bf16.bf16.f32 "
                 "{%0,%1,%2,%3},{%4,%5,%6,%7},{%8,%9},{%0,%1,%2,%3};"
                 : "+f"(c0), "+f"(c1), "+f"(c2), "+f"(c3)
                 : "r"(a.x), "r"(a.y), "r"(a.z), "r"(a.w), "r"(b0), "r"(b1));
}
__device__ __forceinline__ void mma_f16(float& c0, float& c1, float& c2, float& c3,
                                        const uint4& a, unsigned b0, unsigned b1) {
    asm volatile("mma.sync.aligned.m16n8k16.row.col.f32.f16.f16.f32 "
                 "{%0,%1,%2,%3},{%4,%5,%6,%7},{%8,%9},{%0,%1,%2,%3};"
                 : "+f"(c0), "+f"(c1), "+f"(c2), "+f"(c3)
                 : "r"(a.x), "r"(a.y), "r"(a.z), "r"(a.w), "r"(b0), "r"(b1));
}

__device__ __forceinline__ unsigned pack_bf16(float a, float b) {
    __nv_bfloat162 t = __floats2bfloat162_rn(a, b);
    unsigned r; memcpy(&r, &t, 4); return r;
}
__device__ __forceinline__ unsigned pack_f16(float a, float b) {
    __half2 t = __floats2half2_rn(a, b);
    unsigned r; memcpy(&r, &t, 4); return r;
}
__device__ __forceinline__ float bf16_res(float x) {
    return x - __bfloat162float(__float2bfloat16_rn(x));
}

// ---------------- precompute kernels ----------------

__global__ void meanv_kernel(const float* __restrict__ V) {
    __shared__ float red[256];
    const int b = blockIdx.y;
    const int d = blockIdx.x * 64 + (threadIdx.x & 63);
    const int kc = threadIdx.x >> 6;
    const float* vp = V + ((size_t)b * NKT + (size_t)kc * 512) * ND + d;
    float s = 0.f;
    #pragma unroll 8
    for (int k = 0; k < 512; ++k) s += vp[(size_t)k * ND];
    red[threadIdx.x] = s;
    __syncthreads();
    if (threadIdx.x < 64) {
        float tot = red[threadIdx.x] + red[threadIdx.x + 64]
                  + red[threadIdx.x + 128] + red[threadIdx.x + 192];
        g_meanV[b * ND + blockIdx.x * 64 + threadIdx.x] = tot * (1.0f / (float)NKT);
    }
}

__global__ void qpack_kernel(const float* __restrict__ Q) {
    extern __shared__ float sq[];   // [16][1024]
    const int qt = blockIdx.x, b = blockIdx.y, tid = threadIdx.x;
    const float4* src = (const float4*)(Q + ((size_t)(b * NQT + qt * 16)) * ND);
    #pragma unroll
    for (int i = 0; i < 16; ++i) ((float4*)sq)[tid + i * 256] = src[tid + i * 256];
    __syncthreads();
    const size_t base = (size_t)(b * 128 + qt) * 4096;
    #pragma unroll
    for (int it = 0; it < 16; ++it) {
        const int id = tid + it * 256;
        const int rec = id >> 5, lane = id & 31;
        const int ch = rec >> 1, hl = rec & 1;
        const int r0 = lane >> 2, c = ch * 16 + (lane & 3) * 2;
        float v0 = sq[r0 * ND + c],           v1 = sq[r0 * ND + c + 1];
        float v2 = sq[(r0 + 8) * ND + c],     v3 = sq[(r0 + 8) * ND + c + 1];
        float v4 = sq[r0 * ND + c + 8],       v5 = sq[r0 * ND + c + 9];
        float v6 = sq[(r0 + 8) * ND + c + 8], v7 = sq[(r0 + 8) * ND + c + 9];
        if (hl) {
            v0 = bf16_res(v0); v1 = bf16_res(v1); v2 = bf16_res(v2); v3 = bf16_res(v3);
            v4 = bf16_res(v4); v5 = bf16_res(v5); v6 = bf16_res(v6); v7 = bf16_res(v7);
        }
        uint4 o;
        o.x = pack_bf16(v0, v1); o.y = pack_bf16(v2, v3);
        o.z = pack_bf16(v4, v5); o.w = pack_bf16(v6, v7);
        g_QA[base + (size_t)rec * 32 + lane] = o;
    }
}

__global__ void kpack_kernel(const float* __restrict__ K) {
    __shared__ float sk[8 * ND];
    const int nt = blockIdx.x, b = blockIdx.y, tid = threadIdx.x;
    const float4* src = (const float4*)(K + ((size_t)(b * NKT + nt * 8)) * ND);
    #pragma unroll
    for (int i = 0; i < 8; ++i) ((float4*)sk)[tid + i * 256] = src[tid + i * 256];
    __syncthreads();
    const size_t base = (size_t)(b * 256 + nt) * 4096;
    #pragma unroll
    for (int it = 0; it < 16; ++it) {
        const int id = tid + it * 256;
        const int rec = id >> 5, lane = id & 31;
        const int ch = rec >> 1, hl = rec & 1;
        const int n = lane >> 2, c = ch * 16 + (lane & 3) * 2;
        float v0 = sk[n * ND + c],     v1 = sk[n * ND + c + 1];
        float v2 = sk[n * ND + c + 8], v3 = sk[n * ND + c + 9];
        if (hl) { v0 = bf16_res(v0); v1 = bf16_res(v1); v2 = bf16_res(v2); v3 = bf16_res(v3); }
        uint2 o;
        o.x = pack_bf16(v0, v1); o.y = pack_bf16(v2, v3);
        g_KB[base + (size_t)rec * 32 + lane] = o;
    }
}

__global__ void vpack_kernel(const float* __restrict__ V) {
    extern __shared__ float sv[];   // [16][1024]
    const int kc = blockIdx.x, b = blockIdx.y, tid = threadIdx.x;
    const float4* src = (const float4*)(V + ((size_t)(b * NKT + kc * 16)) * ND);
    #pragma unroll
    for (int i = 0; i < 16; ++i) ((float4*)sv)[tid + i * 256] = src[tid + i * 256];
    __syncthreads();
    const size_t base = (size_t)(b * 128 + kc) * 4096;
    #pragma unroll
    for (int it = 0; it < 16; ++it) {
        const int id = tid + it * 256;
        const int nt = id >> 5, lane = id & 31;
        const int g = lane >> 2, k0 = (lane & 3) * 2;
        const int col = nt * 8 + g;
        float v0 = sv[k0 * ND + col],       v1 = sv[(k0 + 1) * ND + col];
        float v2 = sv[(k0 + 8) * ND + col], v3 = sv[(k0 + 9) * ND + col];
        uint2 o;
        o.x = pack_f16(v0, v1); o.y = pack_f16(v2, v3);
        g_VH[base + id] = o;
    }
}

// ---------------- attention kernel ----------------
// 8 warps, BN=64. QK role: qd = w&3 (d-quarter, 16 chunks), cg = w>>2 (4 n8-tiles).
// Q streamed from L1, each fragment amortized over 4 n-tiles (halves Q traffic
// per k vs R10). PV role: warp w owns d-cols [w*128, (w+1)*128).

__global__ void __launch_bounds__(NTHREADS, 2)
attn_kernel(const int* __restrict__ Qlens, const int* __restrict__ Klens,
            float* __restrict__ Out)
{
    __shared__ float sS[2][4][16 * 68];   // [buf][d-quarter][row][col(+pad)]
    __shared__ uint4 sP[2][4][32];        // [buf][k-chunk][lane] P A-fragments (fp16)
    __shared__ float sM[16];
    __shared__ float sL[16];
    __shared__ float sSC[2][16];

    const int tid  = threadIdx.x;
    const int qt   = blockIdx.x;
    const int b    = blockIdx.y;
    const int lane = tid & 31;
    const int w    = tid >> 5;
    const int qd   = w & 3;        // d-quarter (chunks qd*16 .. qd*16+15)
    const int cg   = w >> 2;       // col-group (n-tiles cg*4 .. cg*4+3)
    const int g    = lane >> 2;
    const int tig  = lane & 3;

    const int Qlen = Qlens[b];
    const int Klen = Klens[b];

    // fully masked q-tile -> uniform attention -> mean(V)
    if (qt * 16 >= Qlen) {
        const float4* mv = (const float4*)(g_meanV + b * ND);
        #pragma unroll
        for (int i = 0; i < 16; ++i) {
            const int id = tid + i * 256;
            const int row = id >> 8, c4 = id & 255;
            ((float4*)(Out + ((size_t)(b * NQT + qt * 16 + row)) * ND))[c4] = mv[c4];
        }
        return;
    }

    if (tid < 16) { sM[tid] = NEG_INF; sL[tid] = 0.f; }
    __syncthreads();

    const int nT = (Klen + 63) >> 6;

    float acc[16][4];
    #pragma unroll
    for (int i = 0; i < 16; ++i)
        #pragma unroll
        for (int u = 0; u < 4; ++u) acc[i][u] = 0.f;

    const uint4* Abase = g_QA + (size_t)(b * 128 + qt) * 4096
                         + (size_t)(qd * 16) * 64 + lane;
    const uint2* KbaseB = g_KB + (size_t)(b * 256) * 4096
                          + (size_t)(qd * 16) * 64 + lane;

    for (int t = 0; t < nT; ++t) {
        const int buf = t & 1;

        // ---- QK: 4 n8-tiles x 16 chunks, 3-pass bf16 MMA; Q reused across 4 n-tiles ----
        {
            const uint2* Bp0 = KbaseB + (size_t)(t * 8 + cg * 4)     * 4096;
            const uint2* Bp1 = KbaseB + (size_t)(t * 8 + cg * 4 + 1) * 4096;
            const uint2* Bp2 = KbaseB + (size_t)(t * 8 + cg * 4 + 2) * 4096;
            const uint2* Bp3 = KbaseB + (size_t)(t * 8 + cg * 4 + 3) * 4096;
            float qacc[4][4];
            #pragma unroll
            for (int nt = 0; nt < 4; ++nt)
                #pragma unroll
                for (int u = 0; u < 4; ++u) qacc[nt][u] = 0.f;
            #pragma unroll 4
            for (int ch = 0; ch < 16; ++ch) {
                const uint4 Ah = Abase[ch * 64];
                const uint4 Al = Abase[ch * 64 + 32];
                {
                    const uint2 Bh = Bp0[ch * 64], Bl = Bp0[ch * 64 + 32];
                    mma_bf16(qacc[0][0], qacc[0][1], qacc[0][2], qacc[0][3], Ah, Bh.x, Bh.y);
                    mma_bf16(qacc[0][0], qacc[0][1], qacc[0][2], qacc[0][3], Ah, Bl.x, Bl.y);
                    mma_bf16(qacc[0][0], qacc[0][1], qacc[0][2], qacc[0][3], Al, Bh.x, Bh.y);
                }
                {
                    const uint2 Bh = Bp1[ch * 64], Bl = Bp1[ch * 64 + 32];
                    mma_bf16(qacc[1][0], qacc[1][1], qacc[1][2], qacc[1][3], Ah, Bh.x, Bh.y);
                    mma_bf16(qacc[1][0], qacc[1][1], qacc[1][2], qacc[1][3], Ah, Bl.x, Bl.y);
                    mma_bf16(qacc[1][0], qacc[1][1], qacc[1][2], qacc[1][3], Al, Bh.x, Bh.y);
                }
                {
                    const uint2 Bh = Bp2[ch * 64], Bl = Bp2[ch * 64 + 32];
                    mma_bf16(qacc[2][0], qacc[2][1], qacc[2][2], qacc[2][3], Ah, Bh.x, Bh.y);
                    mma_bf16(qacc[2][0], qacc[2][1], qacc[2][2], qacc[2][3], Ah, Bl.x, Bl.y);
                    mma_bf16(qacc[2][0], qacc[2][1], qacc[2][2], qacc[2][3], Al, Bh.x, Bh.y);
                }
                {
                    const uint2 Bh = Bp3[ch * 64], Bl = Bp3[ch * 64 + 32];
                    mma_bf16(qacc[3][0], qacc[3][1], qacc[3][2], qacc[3][3], Ah, Bh.x, Bh.y);
                    mma_bf16(qacc[3][0], qacc[3][1], qacc[3][2], qacc[3][3], Ah, Bl.x, Bl.y);
                    mma_bf16(qacc[3][0], qacc[3][1], qacc[3][2], qacc[3][3], Al, Bh.x, Bh.y);
                }
            }
            float* S = sS[buf][qd];
            #pragma unroll
            for (int nt = 0; nt < 4; ++nt) {
                const int cA = (cg * 4 + nt) * 8 + tig * 2;
                *(float2*)(S + g * 68 + cA)       = make_float2(qacc[nt][0], qacc[nt][1]);
                *(float2*)(S + (g + 8) * 68 + cA) = make_float2(qacc[nt][2], qacc[nt][3]);
            }
        }
        __syncthreads();   // s1: S partials visible; sP[buf] free (PV of t-2 done)

        // ---- softmax (threads 0..127): sum 4 quarters, fp16 P, sc/m/l ----
        if (tid < 128) {
            const int row = tid >> 3, tc = tid & 7, cb = tc * 8;
            float sv[8] = {0.f, 0.f, 0.f, 0.f, 0.f, 0.f, 0.f, 0.f};
            #pragma unroll
            for (int qq = 0; qq < 4; ++qq) {
                const float* S = sS[buf][qq] + row * 68 + cb;
                const float4 x0 = *(const float4*)S;
                const float4 x1 = *(const float4*)(S + 4);
                sv[0] += x0.x; sv[1] += x0.y; sv[2] += x0.z; sv[3] += x0.w;
                sv[4] += x1.x; sv[5] += x1.y; sv[6] += x1.z; sv[7] += x1.w;
            }
            const int colg = t * 64 + cb;
            #pragma unroll
            for (int i = 0; i < 8; ++i) if (colg + i >= Klen) sv[i] = NEG_INF;
            const float mOld = sM[row];
            float mx = sv[0];
            #pragma unroll
            for (int i = 1; i < 8; ++i) mx = fmaxf(mx, sv[i]);
            mx = fmaxf(mx, __shfl_xor_sync(0xffffffffu, mx, 1));
            mx = fmaxf(mx, __shfl_xor_sync(0xffffffffu, mx, 2));
            mx = fmaxf(mx, __shfl_xor_sync(0xffffffffu, mx, 4));
            const float mN = fmaxf(mOld, mx);
            float p[8];
            float ps = 0.f;
            #pragma unroll
            for (int i = 0; i < 8; ++i) {
                p[i] = __half2float(__float2half_rn(__expf(sv[i] - mN)));
                ps += p[i];
            }
            ps += __shfl_xor_sync(0xffffffffu, ps, 1);
            ps += __shfl_xor_sync(0xffffffffu, ps, 2);
            ps += __shfl_xor_sync(0xffffffffu, ps, 4);
            // write P into A-fragment slots (fp16): chunk = tc>>1, kw = (tc&1)*8
            unsigned* pu = (unsigned*)sP[buf][tc >> 1];
            const int regb = ((tc & 1) << 1) + (row >= 8 ? 1 : 0);
            #pragma unroll
            for (int pi = 0; pi < 4; ++pi)
                pu[((row & 7) * 4 + pi) * 4 + regb] = pack_f16(p[2 * pi], p[2 * pi + 1]);
            if (tc == 0) {
                const float sc = __expf(mOld - mN);   // first tile: exp(-inf)=0
                sSC[buf][row] = sc;
                sM[row] = mN;
                sL[row] = sL[row] * sc + ps;
            }
        }
        __syncthreads();   // s2: P, sc visible

        // ---- PV: rescale acc, then fp16 MMA over 4 k-chunks x 16 n-tiles ----
        {
            const float sc0 = sSC[buf][g];
            const float sc1 = sSC[buf][g + 8];
            #pragma unroll
            for (int i = 0; i < 16; ++i) {
                acc[i][0] *= sc0; acc[i][1] *= sc0;
                acc[i][2] *= sc1; acc[i][3] *= sc1;
            }
            #pragma unroll
            for (int cc = 0; cc < 4; ++cc) {
                const uint4 A = sP[buf][cc][lane];
                const uint2* vb = g_VH + ((size_t)(b * 128 + t * 4 + cc) * 128 + w * 16) * 32 + lane;
                #pragma unroll
                for (int i = 0; i < 16; ++i) {
                    const uint2 B = vb[i * 32];
                    mma_f16(acc[i][0], acc[i][1], acc[i][2], acc[i][3], A, B.x, B.y);
                }
            }
        }
        // no trailing sync: double-buffered S/P/sc; next s1 protects reuse
    }

    // ---- epilogue ----
    const float invA = 1.0f / sL[g];
    const float invB = 1.0f / sL[g + 8];
    const bool vA = (qt * 16 + g) < Qlen;
    const bool vB = (qt * 16 + g + 8) < Qlen;
    float* outA = Out + ((size_t)(b * NQT + qt * 16 + g)) * ND;
    float* outB = Out + ((size_t)(b * NQT + qt * 16 + g + 8)) * ND;
    const float* mv = g_meanV + b * ND;
    #pragma unroll
    for (int i = 0; i < 16; ++i) {
        const int col = w * 128 + i * 8 + tig * 2;
        float2 w0, w1;
        if (vA) { w0.x = acc[i][0] * invA; w0.y = acc[i][1] * invA; }
        else    { w0 = *(const float2*)(mv + col); }
        if (vB) { w1.x = acc[i][2] * invB; w1.y = acc[i][3] * invB; }
        else    { w1 = *(const float2*)(mv + col); }
        *(float2*)(outA + col) = w0;
        *(float2*)(outB + col) = w1;
    }
}

extern "C" void kernel_launch(void* const* d_in, const int* in_sizes, int n_in,
                              void* d_out, int out_size) {
    (void)in_sizes; (void)n_in; (void)out_size;
    const float* Q  = (const float*)d_in[0];
    const float* K  = (const float*)d_in[1];
    const float* V  = (const float*)d_in[2];
    const int*   Ql = (const int*)d_in[3];
    const int*   Kl = (const int*)d_in[4];
    float* Out = (float*)d_out;

    meanv_kernel<<<dim3(ND / 64, NB), 256>>>(V);

    cudaFuncSetAttribute((const void*)qpack_kernel,
                         cudaFuncAttributeMaxDynamicSharedMemorySize, 16 * ND * 4);
    qpack_kernel<<<dim3(128, NB), 256, 16 * ND * 4>>>(Q);
    kpack_kernel<<<dim3(256, NB), 256>>>(K);
    cudaFuncSetAttribute((const void*)vpack_kernel,
                         cudaFuncAttributeMaxDynamicSharedMemorySize, 16 * ND * 4);
    vpack_kernel<<<dim3(128, NB), 256, 16 * ND * 4>>>(V);

    attn_kernel<<<dim3(128, NB), NTHREADS>>>(Ql, Kl, Out);
}

// round 12
// speedup vs baseline: 1.2218x; 1.2218x over previous
#include <cuda_runtime.h>
#include <cuda_bf16.h>
#include <cuda_fp16.h>
#include <cstdint>

#define NB 16
#define NQT 2048
#define NKT 2048
#define ND 1024
#define NTHREADS 256

#define NEG_INF __int_as_float(0xff800000)

// ---- device-global scratch (no cudaMalloc allowed) ----
// Q A-fragments (bf16 hi/lo): [b][qtile16(128)][chunk16(64)][hi/lo(2)][lane(32)] uint4
__device__ uint4 g_QA[16 * 128 * 64 * 2 * 32];
// K B-fragments (bf16 hi/lo): [b][ntile8(256)][chunk16(64)][hi/lo(2)][lane(32)] uint2
__device__ uint2 g_KB[16 * 256 * 64 * 2 * 32];
// V B-fragments (fp16): [b][kchunk16(128)][ntile8(128)][lane(32)] uint2
__device__ uint2 g_VH[16 * 128 * 128 * 32];
__device__ float g_meanV[NB * ND];

__device__ __forceinline__ void mma_bf16(float& c0, float& c1, float& c2, float& c3,
                                         const uint4& a, unsigned b0, unsigned b1) {
    asm volatile("mma.sync.aligned.m16n8k16.row.col.f32.bf16.bf16.f32 "
                 "{%0,%1,%2,%3},{%4,%5,%6,%7},{%8,%9},{%0,%1,%2,%3};"
                 : "+f"(c0), "+f"(c1), "+f"(c2), "+f"(c3)
                 : "r"(a.x), "r"(a.y), "r"(a.z), "r"(a.w), "r"(b0), "r"(b1));
}
__device__ __forceinline__ void mma_f16(float& c0, float& c1, float& c2, float& c3,
                                        const uint4& a, unsigned b0, unsigned b1) {
    asm volatile("mma.sync.aligned.m16n8k16.row.col.f32.f16.f16.f32 "
                 "{%0,%1,%2,%3},{%4,%5,%6,%7},{%8,%9},{%0,%1,%2,%3};"
                 : "+f"(c0), "+f"(c1), "+f"(c2), "+f"(c3)
                 : "r"(a.x), "r"(a.y), "r"(a.z), "r"(a.w), "r"(b0), "r"(b1));
}

__device__ __forceinline__ unsigned pack_bf16(float a, float b) {
    __nv_bfloat162 t = __floats2bfloat162_rn(a, b);
    unsigned r; memcpy(&r, &t, 4); return r;
}
__device__ __forceinline__ unsigned pack_f16(float a, float b) {
    __half2 t = __floats2half2_rn(a, b);
    unsigned r; memcpy(&r, &t, 4); return r;
}
__device__ __forceinline__ float bf16_res(float x) {
    return x - __bfloat162float(__float2bfloat16_rn(x));
}

// ---------------- precompute kernels ----------------

__global__ void meanv_kernel(const float* __restrict__ V) {
    __shared__ float red[256];
    const int b = blockIdx.y;
    const int d = blockIdx.x * 64 + (threadIdx.x & 63);
    const int kc = threadIdx.x >> 6;
    const float* vp = V + ((size_t)b * NKT + (size_t)kc * 512) * ND + d;
    float s = 0.f;
    #pragma unroll 8
    for (int k = 0; k < 512; ++k) s += vp[(size_t)k * ND];
    red[threadIdx.x] = s;
    __syncthreads();
    if (threadIdx.x < 64) {
        float tot = red[threadIdx.x] + red[threadIdx.x + 64]
                  + red[threadIdx.x + 128] + red[threadIdx.x + 192];
        g_meanV[b * ND + blockIdx.x * 64 + threadIdx.x] = tot * (1.0f / (float)NKT);
    }
}

__global__ void qpack_kernel(const float* __restrict__ Q) {
    extern __shared__ float sq[];   // [16][1024]
    const int qt = blockIdx.x, b = blockIdx.y, tid = threadIdx.x;
    const float4* src = (const float4*)(Q + ((size_t)(b * NQT + qt * 16)) * ND);
    #pragma unroll
    for (int i = 0; i < 16; ++i) ((float4*)sq)[tid + i * 256] = src[tid + i * 256];
    __syncthreads();
    const size_t base = (size_t)(b * 128 + qt) * 4096;
    #pragma unroll
    for (int it = 0; it < 16; ++it) {
        const int id = tid + it * 256;
        const int rec = id >> 5, lane = id & 31;
        const int ch = rec >> 1, hl = rec & 1;
        const int r0 = lane >> 2, c = ch * 16 + (lane & 3) * 2;
        float v0 = sq[r0 * ND + c],           v1 = sq[r0 * ND + c + 1];
        float v2 = sq[(r0 + 8) * ND + c],     v3 = sq[(r0 + 8) * ND + c + 1];
        float v4 = sq[r0 * ND + c + 8],       v5 = sq[r0 * ND + c + 9];
        float v6 = sq[(r0 + 8) * ND + c + 8], v7 = sq[(r0 + 8) * ND + c + 9];
        if (hl) {
            v0 = bf16_res(v0); v1 = bf16_res(v1); v2 = bf16_res(v2); v3 = bf16_res(v3);
            v4 = bf16_res(v4); v5 = bf16_res(v5); v6 = bf16_res(v6); v7 = bf16_res(v7);
        }
        uint4 o;
        o.x = pack_bf16(v0, v1); o.y = pack_bf16(v2, v3);
        o.z = pack_bf16(v4, v5); o.w = pack_bf16(v6, v7);
        g_QA[base + (size_t)rec * 32 + lane] = o;
    }
}

__global__ void kpack_kernel(const float* __restrict__ K) {
    __shared__ float sk[8 * ND];
    const int nt = blockIdx.x, b = blockIdx.y, tid = threadIdx.x;
    const float4* src = (const float4*)(K + ((size_t)(b * NKT + nt * 8)) * ND);
    #pragma unroll
    for (int i = 0; i < 8; ++i) ((float4*)sk)[tid + i * 256] = src[tid + i * 256];
    __syncthreads();
    const size_t base = (size_t)(b * 256 + nt) * 4096;
    #pragma unroll
    for (int it = 0; it < 16; ++it) {
        const int id = tid + it * 256;
        const int rec = id >> 5, lane = id & 31;
        const int ch = rec >> 1, hl = rec & 1;
        const int n = lane >> 2, c = ch * 16 + (lane & 3) * 2;
        float v0 = sk[n * ND + c],     v1 = sk[n * ND + c + 1];
        float v2 = sk[n * ND + c + 8], v3 = sk[n * ND + c + 9];
        if (hl) { v0 = bf16_res(v0); v1 = bf16_res(v1); v2 = bf16_res(v2); v3 = bf16_res(v3); }
        uint2 o;
        o.x = pack_bf16(v0, v1); o.y = pack_bf16(v2, v3);
        g_KB[base + (size_t)rec * 32 + lane] = o;
    }
}

__global__ void vpack_kernel(const float* __restrict__ V) {
    extern __shared__ float sv[];   // [16][1024]
    const int kc = blockIdx.x, b = blockIdx.y, tid = threadIdx.x;
    const float4* src = (const float4*)(V + ((size_t)(b * NKT + kc * 16)) * ND);
    #pragma unroll
    for (int i = 0; i < 16; ++i) ((float4*)sv)[tid + i * 256] = src[tid + i * 256];
    __syncthreads();
    const size_t base = (size_t)(b * 128 + kc) * 4096;
    #pragma unroll
    for (int it = 0; it < 16; ++it) {
        const int id = tid + it * 256;
        const int nt = id >> 5, lane = id & 31;
        const int g = lane >> 2, k0 = (lane & 3) * 2;
        const int col = nt * 8 + g;
        float v0 = sv[k0 * ND + col],       v1 = sv[(k0 + 1) * ND + col];
        float v2 = sv[(k0 + 8) * ND + col], v3 = sv[(k0 + 9) * ND + col];
        uint2 o;
        o.x = pack_f16(v0, v1); o.y = pack_f16(v2, v3);
        g_VH[base + id] = o;
    }
}

// ---------------- attention kernel ----------------
// 8 warps, BN=32. QK role: qe = w (d-eighth, 8 chunks), ALL 4 n8-tiles per warp.
// Each Q fragment is loaded by exactly ONE warp per tile (Q L2 traffic 1x).
// PV role: warp w owns d-cols [w*128, (w+1)*128).

__global__ void __launch_bounds__(NTHREADS, 2)
attn_kernel(const int* __restrict__ Qlens, const int* __restrict__ Klens,
            float* __restrict__ Out)
{
    __shared__ float sS[2][8][16 * 36];   // [buf][d-eighth][row][col(+pad)]
    __shared__ uint4 sP[2][2][32];        // [buf][k-chunk][lane] P A-fragments (fp16)
    __shared__ float sM[16];
    __shared__ float sL[16];
    __shared__ float sSC[2][16];

    const int tid  = threadIdx.x;
    const int qt   = blockIdx.x;
    const int b    = blockIdx.y;
    const int lane = tid & 31;
    const int w    = tid >> 5;
    const int g    = lane >> 2;
    const int tig  = lane & 3;

    const int Qlen = Qlens[b];
    const int Klen = Klens[b];

    // fully masked q-tile -> uniform attention -> mean(V)
    if (qt * 16 >= Qlen) {
        const float4* mv = (const float4*)(g_meanV + b * ND);
        #pragma unroll
        for (int i = 0; i < 16; ++i) {
            const int id = tid + i * 256;
            const int row = id >> 8, c4 = id & 255;
            ((float4*)(Out + ((size_t)(b * NQT + qt * 16 + row)) * ND))[c4] = mv[c4];
        }
        return;
    }

    if (tid < 16) { sM[tid] = NEG_INF; sL[tid] = 0.f; }
    __syncthreads();

    const int nT = (Klen + 31) >> 5;

    float acc[16][4];
    #pragma unroll
    for (int i = 0; i < 16; ++i)
        #pragma unroll
        for (int u = 0; u < 4; ++u) acc[i][u] = 0.f;

    // Q/K fragment bases for this warp's d-eighth (chunks w*8 .. w*8+7)
    const uint4* Abase = g_QA + (size_t)(b * 128 + qt) * 4096
                         + (size_t)(w * 8) * 64 + lane;
    const uint2* KbaseB = g_KB + (size_t)(b * 256) * 4096
                          + (size_t)(w * 8) * 64 + lane;

    for (int t = 0; t < nT; ++t) {
        const int buf = t & 1;

        // ---- QK: 4 n8-tiles x 8 chunks; Q loaded ONCE per chunk, reused 4x ----
        {
            const uint2* Bp0 = KbaseB + (size_t)(t * 4)     * 4096;
            const uint2* Bp1 = KbaseB + (size_t)(t * 4 + 1) * 4096;
            const uint2* Bp2 = KbaseB + (size_t)(t * 4 + 2) * 4096;
            const uint2* Bp3 = KbaseB + (size_t)(t * 4 + 3) * 4096;
            float qacc[4][4];
            #pragma unroll
            for (int nt = 0; nt < 4; ++nt)
                #pragma unroll
                for (int u = 0; u < 4; ++u) qacc[nt][u] = 0.f;
            #pragma unroll 2
            for (int ch = 0; ch < 8; ++ch) {
                const uint4 Ah = Abase[ch * 64];
                const uint4 Al = Abase[ch * 64 + 32];
                {
                    const uint2 Bh = Bp0[ch * 64], Bl = Bp0[ch * 64 + 32];
                    mma_bf16(qacc[0][0], qacc[0][1], qacc[0][2], qacc[0][3], Ah, Bh.x, Bh.y);
                    mma_bf16(qacc[0][0], qacc[0][1], qacc[0][2], qacc[0][3], Ah, Bl.x, Bl.y);
                    mma_bf16(qacc[0][0], qacc[0][1], qacc[0][2], qacc[0][3], Al, Bh.x, Bh.y);
                }
                {
                    const uint2 Bh = Bp1[ch * 64], Bl = Bp1[ch * 64 + 32];
                    mma_bf16(qacc[1][0], qacc[1][1], qacc[1][2], qacc[1][3], Ah, Bh.x, Bh.y);
                    mma_bf16(qacc[1][0], qacc[1][1], qacc[1][2], qacc[1][3], Ah, Bl.x, Bl.y);
                    mma_bf16(qacc[1][0], qacc[1][1], qacc[1][2], qacc[1][3], Al, Bh.x, Bh.y);
                }
                {
                    const uint2 Bh = Bp2[ch * 64], Bl = Bp2[ch * 64 + 32];
                    mma_bf16(qacc[2][0], qacc[2][1], qacc[2][2], qacc[2][3], Ah, Bh.x, Bh.y);
                    mma_bf16(qacc[2][0], qacc[2][1], qacc[2][2], qacc[2][3], Ah, Bl.x, Bl.y);
                    mma_bf16(qacc[2][0], qacc[2][1], qacc[2][2], qacc[2][3], Al, Bh.x, Bh.y);
                }
                {
                    const uint2 Bh = Bp3[ch * 64], Bl = Bp3[ch * 64 + 32];
                    mma_bf16(qacc[3][0], qacc[3][1], qacc[3][2], qacc[3][3], Ah, Bh.x, Bh.y);
                    mma_bf16(qacc[3][0], qacc[3][1], qacc[3][2], qacc[3][3], Ah, Bl.x, Bl.y);
                    mma_bf16(qacc[3][0], qacc[3][1], qacc[3][2], qacc[3][3], Al, Bh.x, Bh.y);
                }
            }
            float* S = sS[buf][w];
            #pragma unroll
            for (int nt = 0; nt < 4; ++nt) {
                const int cA = nt * 8 + tig * 2;
                *(float2*)(S + g * 36 + cA)       = make_float2(qacc[nt][0], qacc[nt][1]);
                *(float2*)(S + (g + 8) * 36 + cA) = make_float2(qacc[nt][2], qacc[nt][3]);
            }
        }
        __syncthreads();   // s1: S partials visible; sP[buf] free (PV of t-2 done)

        // ---- softmax (threads 0..127): sum 8 eighth-partials, fp16 P, sc/m/l ----
        if (tid < 128) {
            const int row = tid >> 3, tc = tid & 7, cb = tc * 4;
            float sv[4] = {0.f, 0.f, 0.f, 0.f};
            #pragma unroll
            for (int qq = 0; qq < 8; ++qq) {
                const float4 x = *(const float4*)(sS[buf][qq] + row * 36 + cb);
                sv[0] += x.x; sv[1] += x.y; sv[2] += x.z; sv[3] += x.w;
            }
            const int colg = t * 32 + cb;
            #pragma unroll
            for (int i = 0; i < 4; ++i) if (colg + i >= Klen) sv[i] = NEG_INF;
            const float mOld = sM[row];
            float mx = fmaxf(fmaxf(sv[0], sv[1]), fmaxf(sv[2], sv[3]));
            mx = fmaxf(mx, __shfl_xor_sync(0xffffffffu, mx, 1));
            mx = fmaxf(mx, __shfl_xor_sync(0xffffffffu, mx, 2));
            mx = fmaxf(mx, __shfl_xor_sync(0xffffffffu, mx, 4));
            const float mN = fmaxf(mOld, mx);
            float p[4];
            #pragma unroll
            for (int i = 0; i < 4; ++i)
                p[i] = __half2float(__float2half_rn(__expf(sv[i] - mN)));
            float ps = (p[0] + p[1]) + (p[2] + p[3]);
            ps += __shfl_xor_sync(0xffffffffu, ps, 1);
            ps += __shfl_xor_sync(0xffffffffu, ps, 2);
            ps += __shfl_xor_sync(0xffffffffu, ps, 4);
            // write P into A-fragment slots (fp16)
            const int chunk = cb >> 4;
            const int cw = cb & 15;
            const int reg = ((cw >= 8) ? 2 : 0) + ((row >= 8) ? 1 : 0);
            const int lane0 = (row & 7) * 4 + ((cw & 7) >> 1);
            unsigned* pu = (unsigned*)sP[buf][chunk];
            pu[lane0 * 4 + reg]       = pack_f16(p[0], p[1]);
            pu[(lane0 + 1) * 4 + reg] = pack_f16(p[2], p[3]);
            if (tc == 0) {
                const float sc = __expf(mOld - mN);   // first tile: exp(-inf)=0
                sSC[buf][row] = sc;
                sM[row] = mN;
                sL[row] = sL[row] * sc + ps;
            }
        }
        __syncthreads();   // s2: P, sc visible

        // ---- PV: rescale acc, then fp16 MMA over 2 k-chunks x 16 n-tiles ----
        {
            const float sc0 = sSC[buf][g];
            const float sc1 = sSC[buf][g + 8];
            #pragma unroll
            for (int i = 0; i < 16; ++i) {
                acc[i][0] *= sc0; acc[i][1] *= sc0;
                acc[i][2] *= sc1; acc[i][3] *= sc1;
            }
            #pragma unroll
            for (int cc = 0; cc < 2; ++cc) {
                const uint4 A = sP[buf][cc][lane];
                const uint2* vb = g_VH + ((size_t)(b * 128 + t * 2 + cc) * 128 + w * 16) * 32 + lane;
                #pragma unroll
                for (int i = 0; i < 16; ++i) {
                    const uint2 B = vb[i * 32];
                    mma_f16(acc[i][0], acc[i][1], acc[i][2], acc[i][3], A, B.x, B.y);
                }
            }
        }
        // no trailing sync: double-buffered S/P/sc; next s1 protects reuse
    }

    // ---- epilogue ----
    const float invA = 1.0f / sL[g];
    const float invB = 1.0f / sL[g + 8];
    const bool vA = (qt * 16 + g) < Qlen;
    const bool vB = (qt * 16 + g + 8) < Qlen;
    float* outA = Out + ((size_t)(b * NQT + qt * 16 + g)) * ND;
    float* outB = Out + ((size_t)(b * NQT + qt * 16 + g + 8)) * ND;
    const float* mv = g_meanV + b * ND;
    #pragma unroll
    for (int i = 0; i < 16; ++i) {
        const int col = w * 128 + i * 8 + tig * 2;
        float2 w0, w1;
        if (vA) { w0.x = acc[i][0] * invA; w0.y = acc[i][1] * invA; }
        else    { w0 = *(const float2*)(mv + col); }
        if (vB) { w1.x = acc[i][2] * invB; w1.y = acc[i][3] * invB; }
        else    { w1 = *(const float2*)(mv + col); }
        *(float2*)(outA + col) = w0;
        *(float2*)(outB + col) = w1;
    }
}

extern "C" void kernel_launch(void* const* d_in, const int* in_sizes, int n_in,
                              void* d_out, int out_size) {
    (void)in_sizes; (void)n_in; (void)out_size;
    const float* Q  = (const float*)d_in[0];
    const float* K  = (const float*)d_in[1];
    const float* V  = (const float*)d_in[2];
    const int*   Ql = (const int*)d_in[3];
    const int*   Kl = (const int*)d_in[4];
    float* Out = (float*)d_out;

    meanv_kernel<<<dim3(ND / 64, NB), 256>>>(V);

    cudaFuncSetAttribute((const void*)qpack_kernel,
                         cudaFuncAttributeMaxDynamicSharedMemorySize, 16 * ND * 4);
    qpack_kernel<<<dim3(128, NB), 256, 16 * ND * 4>>>(Q);
    kpack_kernel<<<dim3(256, NB), 256>>>(K);
    cudaFuncSetAttribute((const void*)vpack_kernel,
                         cudaFuncAttributeMaxDynamicSharedMemorySize, 16 * ND * 4);
    vpack_kernel<<<dim3(128, NB), 256, 16 * ND * 4>>>(V);

    attn_kernel<<<dim3(128, NB), NTHREADS>>>(Ql, Kl, Out);
}

// round 13
// speedup vs baseline: 1.7188x; 1.4069x over previous
#include <cuda_runtime.h>
#include <cuda_bf16.h>
#include <cuda_fp16.h>
#include <cstdint>

#define NB 16
#define NQT 2048
#define NKT 2048
#define ND 1024
#define NTHREADS 256

#define NEG_INF __int_as_float(0xff800000)

// ---- device-global scratch (no cudaMalloc allowed) ----
// Q A-fragments (bf16 hi/lo): [b][qtile16(128)][chunk16(64)][hi/lo(2)][lane(32)] uint4
__device__ uint4 g_QA[16 * 128 * 64 * 2 * 32];
// K B-fragments (bf16 hi/lo): [b][ntile8(256)][chunk16(64)][hi/lo(2)][lane(32)] uint2
__device__ uint2 g_KB[16 * 256 * 64 * 2 * 32];
// V B-fragments (fp16): [b][kchunk16(128)][ntile8(128)][lane(32)] uint2
__device__ uint2 g_VH[16 * 128 * 128 * 32];
__device__ float g_meanV[NB * ND];

// ---- dynamic smem byte offsets for attn kernel ----
#define SQ_OFF   0        // uint4[4096] = 65536 B  (Q A-fragments, whole CTA tile)
#define SS_OFF   65536    // float[2][4][16*36] = 18432 B
#define SP_OFF   83968    // uint4[2][2][32] = 2048 B
#define SM_OFF   86016    // float[16]
#define SL_OFF   86080    // float[16]
#define SSC_OFF  86144    // float[2][16]
#define SMEM_BYTES 86272

__device__ __forceinline__ void mma_bf16(float& c0, float& c1, float& c2, float& c3,
                                         const uint4& a, unsigned b0, unsigned b1) {
    asm volatile("mma.sync.aligned.m16n8k16.row.col.f32.bf16.bf16.f32 "
                 "{%0,%1,%2,%3},{%4,%5,%6,%7},{%8,%9},{%0,%1,%2,%3};"
                 : "+f"(c0), "+f"(c1), "+f"(c2), "+f"(c3)
                 : "r"(a.x), "r"(a.y), "r"(a.z), "r"(a.w), "r"(b0), "r"(b1));
}
__device__ __forceinline__ void mma_f16(float& c0, float& c1, float& c2, float& c3,
                                        const uint4& a, unsigned b0, unsigned b1) {
    asm volatile("mma.sync.aligned.m16n8k16.row.col.f32.f16.f16.f32 "
                 "{%0,%1,%2,%3},{%4,%5,%6,%7},{%8,%9},{%0,%1,%2,%3};"
                 : "+f"(c0), "+f"(c1), "+f"(c2), "+f"(c3)
                 : "r"(a.x), "r"(a.y), "r"(a.z), "r"(a.w), "r"(b0), "r"(b1));
}

__device__ __forceinline__ unsigned pack_bf16(float a, float b) {
    __nv_bfloat162 t = __floats2bfloat162_rn(a, b);
    unsigned r; memcpy(&r, &t, 4); return r;
}
__device__ __forceinline__ unsigned pack_f16(float a, float b) {
    __half2 t = __floats2half2_rn(a, b);
    unsigned r; memcpy(&r, &t, 4); return r;
}
__device__ __forceinline__ float bf16_res(float x) {
    return x - __bfloat162float(__float2bfloat16_rn(x));
}

// ---------------- precompute kernels ----------------

__global__ void meanv_kernel(const float* __restrict__ V) {
    __shared__ float red[256];
    const int b = blockIdx.y;
    const int d = blockIdx.x * 64 + (threadIdx.x & 63);
    const int kc = threadIdx.x >> 6;
    const float* vp = V + ((size_t)b * NKT + (size_t)kc * 512) * ND + d;
    float s = 0.f;
    #pragma unroll 8
    for (int k = 0; k < 512; ++k) s += vp[(size_t)k * ND];
    red[threadIdx.x] = s;
    __syncthreads();
    if (threadIdx.x < 64) {
        float tot = red[threadIdx.x] + red[threadIdx.x + 64]
                  + red[threadIdx.x + 128] + red[threadIdx.x + 192];
        g_meanV[b * ND + blockIdx.x * 64 + threadIdx.x] = tot * (1.0f / (float)NKT);
    }
}

__global__ void qpack_kernel(const float* __restrict__ Q) {
    extern __shared__ float sq[];   // [16][1024]
    const int qt = blockIdx.x, b = blockIdx.y, tid = threadIdx.x;
    const float4* src = (const float4*)(Q + ((size_t)(b * NQT + qt * 16)) * ND);
    #pragma unroll
    for (int i = 0; i < 16; ++i) ((float4*)sq)[tid + i * 256] = src[tid + i * 256];
    __syncthreads();
    const size_t base = (size_t)(b * 128 + qt) * 4096;
    #pragma unroll
    for (int it = 0; it < 16; ++it) {
        const int id = tid + it * 256;
        const int rec = id >> 5, lane = id & 31;
        const int ch = rec >> 1, hl = rec & 1;
        const int r0 = lane >> 2, c = ch * 16 + (lane & 3) * 2;
        float v0 = sq[r0 * ND + c],           v1 = sq[r0 * ND + c + 1];
        float v2 = sq[(r0 + 8) * ND + c],     v3 = sq[(r0 + 8) * ND + c + 1];
        float v4 = sq[r0 * ND + c + 8],       v5 = sq[r0 * ND + c + 9];
        float v6 = sq[(r0 + 8) * ND + c + 8], v7 = sq[(r0 + 8) * ND + c + 9];
        if (hl) {
            v0 = bf16_res(v0); v1 = bf16_res(v1); v2 = bf16_res(v2); v3 = bf16_res(v3);
            v4 = bf16_res(v4); v5 = bf16_res(v5); v6 = bf16_res(v6); v7 = bf16_res(v7);
        }
        uint4 o;
        o.x = pack_bf16(v0, v1); o.y = pack_bf16(v2, v3);
        o.z = pack_bf16(v4, v5); o.w = pack_bf16(v6, v7);
        g_QA[base + (size_t)rec * 32 + lane] = o;
    }
}

__global__ void kpack_kernel(const float* __restrict__ K) {
    __shared__ float sk[8 * ND];
    const int nt = blockIdx.x, b = blockIdx.y, tid = threadIdx.x;
    const float4* src = (const float4*)(K + ((size_t)(b * NKT + nt * 8)) * ND);
    #pragma unroll
    for (int i = 0; i < 8; ++i) ((float4*)sk)[tid + i * 256] = src[tid + i * 256];
    __syncthreads();
    const size_t base = (size_t)(b * 256 + nt) * 4096;
    #pragma unroll
    for (int it = 0; it < 16; ++it) {
        const int id = tid + it * 256;
        const int rec = id >> 5, lane = id & 31;
        const int ch = rec >> 1, hl = rec & 1;
        const int n = lane >> 2, c = ch * 16 + (lane & 3) * 2;
        float v0 = sk[n * ND + c],     v1 = sk[n * ND + c + 1];
        float v2 = sk[n * ND + c + 8], v3 = sk[n * ND + c + 9];
        if (hl) { v0 = bf16_res(v0); v1 = bf16_res(v1); v2 = bf16_res(v2); v3 = bf16_res(v3); }
        uint2 o;
        o.x = pack_bf16(v0, v1); o.y = pack_bf16(v2, v3);
        g_KB[base + (size_t)rec * 32 + lane] = o;
    }
}

__global__ void vpack_kernel(const float* __restrict__ V) {
    extern __shared__ float sv[];   // [16][1024]
    const int kc = blockIdx.x, b = blockIdx.y, tid = threadIdx.x;
    const float4* src = (const float4*)(V + ((size_t)(b * NKT + kc * 16)) * ND);
    #pragma unroll
    for (int i = 0; i < 16; ++i) ((float4*)sv)[tid + i * 256] = src[tid + i * 256];
    __syncthreads();
    const size_t base = (size_t)(b * 128 + kc) * 4096;
    #pragma unroll
    for (int it = 0; it < 16; ++it) {
        const int id = tid + it * 256;
        const int nt = id >> 5, lane = id & 31;
        const int g = lane >> 2, k0 = (lane & 3) * 2;
        const int col = nt * 8 + g;
        float v0 = sv[k0 * ND + col],       v1 = sv[(k0 + 1) * ND + col];
        float v2 = sv[(k0 + 8) * ND + col], v3 = sv[(k0 + 9) * ND + col];
        uint2 o;
        o.x = pack_f16(v0, v1); o.y = pack_f16(v2, v3);
        g_VH[base + id] = o;
    }
}

// ---------------- attention kernel ----------------
// R10 structure (8 warps, BN=32, qd = w&3, cg = w>>2, 2 n8-tiles/warp) with ONE
// change: the CTA's Q A-fragments (64 KB) are staged in shared memory once, so
// Q contributes no per-tile L2 traffic (was ~40% of the 320 KB/tile stream).

__global__ void __launch_bounds__(NTHREADS, 2)
attn_kernel(const int* __restrict__ Qlens, const int* __restrict__ Klens,
            float* __restrict__ Out)
{
    extern __shared__ char smem[];
    uint4* sQ  = (uint4*)(smem + SQ_OFF);          // [4096] = [chunk64][hi/lo2][lane32]
    float* sS  = (float*)(smem + SS_OFF);          // [2][4][16*36]
    uint4* sP  = (uint4*)(smem + SP_OFF);          // [2][2][32]
    float* sM  = (float*)(smem + SM_OFF);          // [16]
    float* sL  = (float*)(smem + SL_OFF);          // [16]
    float* sSC = (float*)(smem + SSC_OFF);         // [2][16]

    const int tid  = threadIdx.x;
    const int qt   = blockIdx.x;
    const int b    = blockIdx.y;
    const int lane = tid & 31;
    const int w    = tid >> 5;
    const int qd   = w & 3;        // d-quarter (chunks qd*16 .. qd*16+15)
    const int cg   = w >> 2;       // col-group (n-tiles cg*2, cg*2+1)
    const int g    = lane >> 2;
    const int tig  = lane & 3;

    const int Qlen = Qlens[b];
    const int Klen = Klens[b];

    // fully masked q-tile -> uniform attention -> mean(V)
    if (qt * 16 >= Qlen) {
        const float4* mv = (const float4*)(g_meanV + b * ND);
        #pragma unroll
        for (int i = 0; i < 16; ++i) {
            const int id = tid + i * 256;
            const int row = id >> 8, c4 = id & 255;
            ((float4*)(Out + ((size_t)(b * NQT + qt * 16 + row)) * ND))[c4] = mv[c4];
        }
        return;
    }

    // ---- stage this CTA's Q A-fragments into smem (once) ----
    {
        const uint4* src = g_QA + (size_t)(b * 128 + qt) * 4096;
        #pragma unroll
        for (int i = 0; i < 16; ++i) sQ[tid + i * 256] = src[tid + i * 256];
    }
    if (tid < 16) { sM[tid] = NEG_INF; sL[tid] = 0.f; }
    __syncthreads();

    const int nT = (Klen + 31) >> 5;

    float acc[16][4];
    #pragma unroll
    for (int i = 0; i < 16; ++i)
        #pragma unroll
        for (int u = 0; u < 4; ++u) acc[i][u] = 0.f;

    // Q fragments now read from smem; K fragments stream from gmem/L2
    const uint4* Abase = sQ + (size_t)(qd * 16) * 64 + lane;
    const uint2* KbaseB = g_KB + (size_t)(b * 256) * 4096
                          + (size_t)(qd * 16) * 64 + lane;

    for (int t = 0; t < nT; ++t) {
        const int buf = t & 1;

        // ---- QK: 2 n8-tiles x 16 chunks, 3-pass bf16 MMA; Q from smem ----
        {
            const uint2* Bp0 = KbaseB + (size_t)(t * 4 + cg * 2)     * 4096;
            const uint2* Bp1 = KbaseB + (size_t)(t * 4 + cg * 2 + 1) * 4096;
            float a0 = 0.f, a1 = 0.f, a2 = 0.f, a3 = 0.f;   // n-tile 0
            float b0 = 0.f, b1 = 0.f, b2 = 0.f, b3 = 0.f;   // n-tile 1
            #pragma unroll 4
            for (int ch = 0; ch < 16; ++ch) {
                const uint4 Ah = Abase[ch * 64];
                const uint4 Al = Abase[ch * 64 + 32];
                const uint2 B0h = Bp0[ch * 64];
                const uint2 B0l = Bp0[ch * 64 + 32];
                const uint2 B1h = Bp1[ch * 64];
                const uint2 B1l = Bp1[ch * 64 + 32];
                mma_bf16(a0, a1, a2, a3, Ah, B0h.x, B0h.y);
                mma_bf16(a0, a1, a2, a3, Ah, B0l.x, B0l.y);
                mma_bf16(a0, a1, a2, a3, Al, B0h.x, B0h.y);
                mma_bf16(b0, b1, b2, b3, Ah, B1h.x, B1h.y);
                mma_bf16(b0, b1, b2, b3, Ah, B1l.x, B1l.y);
                mma_bf16(b0, b1, b2, b3, Al, B1h.x, B1h.y);
            }
            float* S = sS + (size_t)(buf * 4 + qd) * (16 * 36);
            const int c0 = (cg * 2) * 8 + tig * 2;
            *(float2*)(S + g * 36 + c0)           = make_float2(a0, a1);
            *(float2*)(S + (g + 8) * 36 + c0)     = make_float2(a2, a3);
            *(float2*)(S + g * 36 + c0 + 8)       = make_float2(b0, b1);
            *(float2*)(S + (g + 8) * 36 + c0 + 8) = make_float2(b2, b3);
        }
        __syncthreads();   // s1: S partials visible; sP[buf] free (PV of t-2 done)

        // ---- softmax (threads 0..127): sum 4 quarters, fp16 P, sc/m/l ----
        if (tid < 128) {
            const int row = tid >> 3, tc = tid & 7, cb = tc * 4;
            const float4 s0 = *(const float4*)(sS + (size_t)(buf * 4 + 0) * (16 * 36) + row * 36 + cb);
            const float4 s1 = *(const float4*)(sS + (size_t)(buf * 4 + 1) * (16 * 36) + row * 36 + cb);
            const float4 s2 = *(const float4*)(sS + (size_t)(buf * 4 + 2) * (16 * 36) + row * 36 + cb);
            const float4 s3 = *(const float4*)(sS + (size_t)(buf * 4 + 3) * (16 * 36) + row * 36 + cb);
            float sv[4] = {(s0.x + s1.x) + (s2.x + s3.x),
                           (s0.y + s1.y) + (s2.y + s3.y),
                           (s0.z + s1.z) + (s2.z + s3.z),
                           (s0.w + s1.w) + (s2.w + s3.w)};
            const int colg = t * 32 + cb;
            #pragma unroll
            for (int i = 0; i < 4; ++i) if (colg + i >= Klen) sv[i] = NEG_INF;
            const float mOld = sM[row];
            float mx = fmaxf(fmaxf(sv[0], sv[1]), fmaxf(sv[2], sv[3]));
            mx = fmaxf(mx, __shfl_xor_sync(0xffffffffu, mx, 1));
            mx = fmaxf(mx, __shfl_xor_sync(0xffffffffu, mx, 2));
            mx = fmaxf(mx, __shfl_xor_sync(0xffffffffu, mx, 4));
            const float mN = fmaxf(mOld, mx);
            float p[4];
            #pragma unroll
            for (int i = 0; i < 4; ++i)
                p[i] = __half2float(__float2half_rn(__expf(sv[i] - mN)));
            float ps = (p[0] + p[1]) + (p[2] + p[3]);
            ps += __shfl_xor_sync(0xffffffffu, ps, 1);
            ps += __shfl_xor_sync(0xffffffffu, ps, 2);
            ps += __shfl_xor_sync(0xffffffffu, ps, 4);
            // write P into A-fragment slots (fp16)
            const int chunk = cb >> 4;
            const int cw = cb & 15;
            const int reg = ((cw >= 8) ? 2 : 0) + ((row >= 8) ? 1 : 0);
            const int lane0 = (row & 7) * 4 + ((cw & 7) >> 1);
            unsigned* pu = (unsigned*)(sP + (size_t)(buf * 2 + chunk) * 32);
            pu[lane0 * 4 + reg]       = pack_f16(p[0], p[1]);
            pu[(lane0 + 1) * 4 + reg] = pack_f16(p[2], p[3]);
            if (tc == 0) {
                const float sc = __expf(mOld - mN);   // first tile: exp(-inf)=0
                sSC[buf * 16 + row] = sc;
                sM[row] = mN;
                sL[row] = sL[row] * sc + ps;
            }
        }
        __syncthreads();   // s2: P, sc visible

        // ---- PV: rescale acc, then fp16 MMA over 2 k-chunks x 16 n-tiles ----
        {
            const float sc0 = sSC[buf * 16 + g];
            const float sc1 = sSC[buf * 16 + g + 8];
            #pragma unroll
            for (int i = 0; i < 16; ++i) {
                acc[i][0] *= sc0; acc[i][1] *= sc0;
                acc[i][2] *= sc1; acc[i][3] *= sc1;
            }
            #pragma unroll
            for (int cc = 0; cc < 2; ++cc) {
                const uint4 A = sP[(buf * 2 + cc) * 32 + lane];
                const uint2* vb = g_VH + ((size_t)(b * 128 + t * 2 + cc) * 128 + w * 16) * 32 + lane;
                #pragma unroll
                for (int i = 0; i < 16; ++i) {
                    const uint2 B = vb[i * 32];
                    mma_f16(acc[i][0], acc[i][1], acc[i][2], acc[i][3], A, B.x, B.y);
                }
            }
        }
        // no trailing sync: double-buffered S/P/sc; next s1 protects reuse
    }

    // ---- epilogue ----
    const float invA = 1.0f / sL[g];
    const float invB = 1.0f / sL[g + 8];
    const bool vA = (qt * 16 + g) < Qlen;
    const bool vB = (qt * 16 + g + 8) < Qlen;
    float* outA = Out + ((size_t)(b * NQT + qt * 16 + g)) * ND;
    float* outB = Out + ((size_t)(b * NQT + qt * 16 + g + 8)) * ND;
    const float* mv = g_meanV + b * ND;
    #pragma unroll
    for (int i = 0; i < 16; ++i) {
        const int col = w * 128 + i * 8 + tig * 2;
        float2 w0, w1;
        if (vA) { w0.x = acc[i][0] * invA; w0.y = acc[i][1] * invA; }
        else    { w0 = *(const float2*)(mv + col); }
        if (vB) { w1.x = acc[i][2] * invB; w1.y = acc[i][3] * invB; }
        else    { w1 = *(const float2*)(mv + col); }
        *(float2*)(outA + col) = w0;
        *(float2*)(outB + col) = w1;
    }
}

extern "C" void kernel_launch(void* const* d_in, const int* in_sizes, int n_in,
                              void* d_out, int out_size) {
    (void)in_sizes; (void)n_in; (void)out_size;
    const float* Q  = (const float*)d_in[0];
    const float* K  = (const float*)d_in[1];
    const float* V  = (const float*)d_in[2];
    const int*   Ql = (const int*)d_in[3];
    const int*   Kl = (const int*)d_in[4];
    float* Out = (float*)d_out;

    meanv_kernel<<<dim3(ND / 64, NB), 256>>>(V);

    cudaFuncSetAttribute((const void*)qpack_kernel,
                         cudaFuncAttributeMaxDynamicSharedMemorySize, 16 * ND * 4);
    qpack_kernel<<<dim3(128, NB), 256, 16 * ND * 4>>>(Q);
    kpack_kernel<<<dim3(256, NB), 256>>>(K);
    cudaFuncSetAttribute((const void*)vpack_kernel,
                         cudaFuncAttributeMaxDynamicSharedMemorySize, 16 * ND * 4);
    vpack_kernel<<<dim3(128, NB), 256, 16 * ND * 4>>>(V);

    cudaFuncSetAttribute((const void*)attn_kernel,
                         cudaFuncAttributeMaxDynamicSharedMemorySize, SMEM_BYTES);
    attn_kernel<<<dim3(128, NB), NTHREADS, SMEM_BYTES>>>(Ql, Kl, Out);
}